// round 16
// baseline (speedup 1.0000x reference)
#include <cuda_runtime.h>
#include <cuda_bf16.h>
#include <math_constants.h>
#include <cstdint>

// Problem constants
#define NWAY  64
#define KSHOT 16
#define QSHOT 512
#define TOPK  20
#define DIM   768
#define NSUP  (NWAY * KSHOT)   // 1024 support rows
#define NQRY  (NWAY * QSHOT)   // 32768 query rows
#define CAP   1024             // max candidates per row
#define HSHIFT 16              // histogram key shift (R15-proven)

// Scratch (static device globals — allocation-free kernel_launch).
__device__ __nv_bfloat16 g_dist[(size_t)NSUP * NQRY];  // APPROX sims, bf16 (64 MB)
__device__ float    g_x2[NSUP];
__device__ float    g_y2[NQRY];
__device__ int      g_y2max_i;                  // bit-pattern max of y2 (atomicMax, idempotent)
__device__ unsigned g_rowmin_key[NSUP];         // per-row min approx, fkey encoding
__device__ int      g_topk[NSUP * TOPK];

// ---------------------------------------------------------------------------
// Total-order float key (monotone over ALL floats incl. negatives) + inverse.
// ---------------------------------------------------------------------------
__device__ __forceinline__ unsigned fkey(float f) {
    unsigned u = __float_as_uint(f);
    return (u & 0x80000000u) ? ~u : (u | 0x80000000u);
}
__device__ __forceinline__ float fkey_inv(unsigned k) {
    unsigned u = (k & 0x80000000u) ? (k & 0x7FFFFFFFu) : ~k;
    return __uint_as_float(u);
}

// ---------------------------------------------------------------------------
// Kernel 1: row squared-norm, VF4/IC2 FMA structure (frozen since R7).
// Support variant also re-initializes g_rowmin_key each launch (runs before
// the GEMM, which atomicMins into it).
// ---------------------------------------------------------------------------
template <bool TO_X2>
__global__ __launch_bounds__(256)
void rownorm_kernel(const float* __restrict__ v, int nrows) {
    if (TO_X2) {
        int gid = blockIdx.x * 256 + threadIdx.x;
        if (gid < NSUP) g_rowmin_key[gid] = 0xFFFFFFFFu;
    }
    const int lane = threadIdx.x & 31;
    const int wrp  = threadIdx.x >> 5;
    const int row  = blockIdx.x * 8 + wrp;
    if (row >= nrows) return;

    const float* p = v + (size_t)row * DIM;
    float a = 0.f;
    const int k = lane & 7;
#pragma unroll 8
    for (int i = 0; i < 96; i++) {
        float e = __ldg(p + 8 * i + k);
        if (lane < 8) a = __fmaf_rn(e, e, a);
    }
    const unsigned FULL = 0xFFFFFFFFu;
    const int l = lane & 3;
    float s0 = __shfl_sync(FULL, a, l);
    float s1 = __shfl_sync(FULL, a, l + 4);
    float w  = __fadd_rn(s0, s1);
    float w0 = __shfl_sync(FULL, w, 0);
    float w1 = __shfl_sync(FULL, w, 1);
    float w2 = __shfl_sync(FULL, w, 2);
    float w3 = __shfl_sync(FULL, w, 3);
    if (lane == 0) {
        float r = __fadd_rn(__fadd_rn(w0, w1), __fadd_rn(w2, w3));
        if (TO_X2) {
            g_x2[row] = r;
        } else {
            g_y2[row] = r;
            atomicMax(&g_y2max_i, __float_as_int(r));
        }
    }
}

// ---------------------------------------------------------------------------
// Kernel 2: APPROX GEMM on tensor cores (bf16 mma.sync m16n8k16, f32 accum).
// Epilogue now (a) stores bf16 sims (half the write traffic) and (b) computes
// the per-row min in-register -> smem fkey atomicMin -> global atomicMin
// (removes select's dedicated min pass).
// ---------------------------------------------------------------------------
__device__ __forceinline__ uint32_t pk_bf16x2(float x, float y) {
    __nv_bfloat162 h = __float22bfloat162_rn(make_float2(x, y));
    return *reinterpret_cast<uint32_t*>(&h);
}

__device__ __forceinline__ void mma16816(float* c, const uint32_t* a, const uint32_t* b) {
    asm volatile(
        "mma.sync.aligned.m16n8k16.row.col.f32.bf16.bf16.f32 "
        "{%0,%1,%2,%3}, {%4,%5,%6,%7}, {%8,%9}, {%0,%1,%2,%3};"
        : "+f"(c[0]), "+f"(c[1]), "+f"(c[2]), "+f"(c[3])
        : "r"(a[0]), "r"(a[1]), "r"(a[2]), "r"(a[3]), "r"(b[0]), "r"(b[1]));
}

#define APAD 12

__global__ __launch_bounds__(256)
void approx_gemm_kernel(const float* __restrict__ A,
                        const float* __restrict__ B)
{
    __shared__ uint32_t As[2][128][APAD];
    __shared__ uint32_t Bs[2][128][APAD];
    __shared__ unsigned s_rmin[128];

    const int tid  = threadIdx.x;
    const int lane = tid & 31;
    const int wid  = tid >> 5;
    const int wm   = (wid & 3) * 32;
    const int wn   = (wid >> 2) * 64;
    const int m0   = blockIdx.y * 128;
    const int n0   = blockIdx.x * 128;

    if (tid < 128) s_rmin[tid] = 0xFFFFFFFFu;

    const int r    = tid >> 1;
    const int half = tid & 1;
    const float* Ag = A + (size_t)(m0 + r) * DIM + half * 8;
    const float* Bg = B + (size_t)(n0 + r) * DIM + half * 8;

    float acc[2][8][4];
#pragma unroll
    for (int i = 0; i < 2; i++)
#pragma unroll
        for (int j = 0; j < 8; j++)
#pragma unroll
            for (int q = 0; q < 4; q++) acc[i][j][q] = 0.f;

    float4 fa0, fa1, fb0, fb1;

    fa0 = *reinterpret_cast<const float4*>(Ag);
    fa1 = *reinterpret_cast<const float4*>(Ag + 4);
    fb0 = *reinterpret_cast<const float4*>(Bg);
    fb1 = *reinterpret_cast<const float4*>(Bg + 4);
    {
        uint32_t* ar = &As[0][r][half * 4];
        ar[0] = pk_bf16x2(fa0.x, fa0.y); ar[1] = pk_bf16x2(fa0.z, fa0.w);
        ar[2] = pk_bf16x2(fa1.x, fa1.y); ar[3] = pk_bf16x2(fa1.z, fa1.w);
        uint32_t* br = &Bs[0][r][half * 4];
        br[0] = pk_bf16x2(fb0.x, fb0.y); br[1] = pk_bf16x2(fb0.z, fb0.w);
        br[2] = pk_bf16x2(fb1.x, fb1.y); br[3] = pk_bf16x2(fb1.z, fb1.w);
    }
    __syncthreads();

    const int NSTEP = DIM / 16;
    for (int ks = 0; ks < NSTEP; ks++) {
        const int s = ks & 1;
        const bool more = (ks + 1) < NSTEP;
        if (more) {
            const int ko = (ks + 1) * 16;
            fa0 = *reinterpret_cast<const float4*>(Ag + ko);
            fa1 = *reinterpret_cast<const float4*>(Ag + ko + 4);
            fb0 = *reinterpret_cast<const float4*>(Bg + ko);
            fb1 = *reinterpret_cast<const float4*>(Bg + ko + 4);
        }

        uint32_t afr[2][4], bfr[8][2];
        const int rg = lane >> 2, cg = lane & 3;
#pragma unroll
        for (int mf = 0; mf < 2; mf++) {
            const int rw = wm + mf * 16 + rg;
            afr[mf][0] = As[s][rw][cg];
            afr[mf][1] = As[s][rw + 8][cg];
            afr[mf][2] = As[s][rw][cg + 4];
            afr[mf][3] = As[s][rw + 8][cg + 4];
        }
#pragma unroll
        for (int f = 0; f < 8; f++) {
            const int col = wn + f * 8 + rg;
            bfr[f][0] = Bs[s][col][cg];
            bfr[f][1] = Bs[s][col][cg + 4];
        }
#pragma unroll
        for (int mf = 0; mf < 2; mf++)
#pragma unroll
            for (int f = 0; f < 8; f++)
                mma16816(acc[mf][f], afr[mf], bfr[f]);

        if (more) {
            const int ns = s ^ 1;
            uint32_t* ar = &As[ns][r][half * 4];
            ar[0] = pk_bf16x2(fa0.x, fa0.y); ar[1] = pk_bf16x2(fa0.z, fa0.w);
            ar[2] = pk_bf16x2(fa1.x, fa1.y); ar[3] = pk_bf16x2(fa1.z, fa1.w);
            uint32_t* br = &Bs[ns][r][half * 4];
            br[0] = pk_bf16x2(fb0.x, fb0.y); br[1] = pk_bf16x2(fb0.z, fb0.w);
            br[2] = pk_bf16x2(fb1.x, fb1.y); br[3] = pk_bf16x2(fb1.z, fb1.w);
        }
        __syncthreads();
    }

    // epilogue: approx = y2[n] - 2*acc  -> bf16 store + per-row min tracking
    const int rg = lane >> 2, cg = lane & 3;
    float mn4[4] = {CUDART_INF_F, CUDART_INF_F, CUDART_INF_F, CUDART_INF_F};
#pragma unroll
    for (int f = 0; f < 8; f++) {
        const int n = n0 + wn + f * 8 + 2 * cg;
        float2 y2p = *reinterpret_cast<const float2*>(&g_y2[n]);
#pragma unroll
        for (int mf = 0; mf < 2; mf++) {
            const int mrow = m0 + wm + mf * 16 + rg;
            float* c = acc[mf][f];
            float2 o0 = make_float2(y2p.x - 2.f * c[0], y2p.y - 2.f * c[1]);
            float2 o1 = make_float2(y2p.x - 2.f * c[2], y2p.y - 2.f * c[3]);
            mn4[mf * 2 + 0] = fminf(mn4[mf * 2 + 0], fminf(o0.x, o0.y));
            mn4[mf * 2 + 1] = fminf(mn4[mf * 2 + 1], fminf(o1.x, o1.y));
            *reinterpret_cast<__nv_bfloat162*>(&g_dist[(size_t)mrow * NQRY + n]) =
                __float22bfloat162_rn(o0);
            *reinterpret_cast<__nv_bfloat162*>(&g_dist[(size_t)(mrow + 8) * NQRY + n]) =
                __float22bfloat162_rn(o1);
        }
    }
#pragma unroll
    for (int mf = 0; mf < 2; mf++) {
        atomicMin(&s_rmin[wm + mf * 16 + rg],     fkey(mn4[mf * 2 + 0]));
        atomicMin(&s_rmin[wm + mf * 16 + rg + 8], fkey(mn4[mf * 2 + 1]));
    }
    __syncthreads();
    if (tid < 128) atomicMin(&g_rowmin_key[m0 + tid], s_rmin[tid]);
}

// ---------------------------------------------------------------------------
// Kernel 3: HISTOGRAM select (2 passes over bf16 sims; min precomputed by
// the GEMM). Margin += 16 covers the two bf16-quantization half-ulps
// (histogram rank + collect compare) on top of the R12-proven bound.
// ---------------------------------------------------------------------------
#define SEL_THREADS 256

__global__ __launch_bounds__(SEL_THREADS)
void select_kernel(const float* __restrict__ A, const float* __restrict__ B) {
    __shared__ int            s_hist[256];
    __shared__ float          s_arow[DIM];
    __shared__ unsigned short scand[CAP];
    __shared__ float          scex[CAP];
    __shared__ float          s20v[TOPK];
    __shared__ int            s20i[TOPK];
    __shared__ double         s20d[TOPK];
    __shared__ int            s_cnt;
    __shared__ float          s_thr;

    const int row = blockIdx.x;
    const int t   = threadIdx.x;
    const __nv_bfloat16* drow = g_dist + (size_t)row * NQRY;
    const uint4* d8 = reinterpret_cast<const uint4*>(drow);   // 8 bf16 per load

    if (t < 256) s_hist[t] = 0;
    if (t < TOPK) { s20v[t] = CUDART_INF_F; s20i[t] = 0; }   // crash guard
    if (t < DIM / 4)
        reinterpret_cast<float4*>(s_arow)[t] =
            reinterpret_cast<const float4*>(A + (size_t)row * DIM)[t];
    __syncthreads();

    const unsigned bk = g_rowmin_key[row] >> HSHIFT;

    // ---- pass 1: histogram over bf16 sims ----
    for (int i = t; i < NQRY / 8; i += SEL_THREADS) {
        uint4 u = d8[i];
        unsigned uw[4] = {u.x, u.y, u.z, u.w};
#pragma unroll
        for (int q = 0; q < 4; q++) {
            float2 v = __bfloat1622float2(*reinterpret_cast<__nv_bfloat162*>(&uw[q]));
            int b0 = (int)((fkey(v.x) >> HSHIFT) - bk);
            int b1 = (int)((fkey(v.y) >> HSHIFT) - bk);
            if ((unsigned)b0 < 255u) atomicAdd(&s_hist[b0], 1);
            if ((unsigned)b1 < 255u) atomicAdd(&s_hist[b1], 1);
        }
    }
    __syncthreads();
    if (t == 0) {
        int cum = 0, b20 = 254;
        for (int b = 0; b < 255; b++) {
            cum += s_hist[b];
            if (cum >= TOPK) { b20 = b; break; }
        }
        float edge  = fkey_inv((bk + (unsigned)b20 + 1u) << HSHIFT);
        float y2max = __int_as_float(g_y2max_i);
        // bf16 margin (R12-proven) + 16 for two bf16-quantization half-ulps
        s_thr = edge + 0.03125f * sqrtf(g_x2[row] * y2max) + 16.05f;
        s_cnt = 0;
    }
    __syncthreads();
    const float thr = s_thr;

    // ---- pass 2: collect candidates ----
    for (int i = t; i < NQRY / 8; i += SEL_THREADS) {
        uint4 u = d8[i];
        unsigned uw[4] = {u.x, u.y, u.z, u.w};
        const int base = i * 8;
#pragma unroll
        for (int q = 0; q < 4; q++) {
            float2 v = __bfloat1622float2(*reinterpret_cast<__nv_bfloat162*>(&uw[q]));
            if (v.x <= thr) { int p = atomicAdd(&s_cnt, 1); if (p < CAP) scand[p] = (unsigned short)(base + 2 * q); }
            if (v.y <= thr) { int p = atomicAdd(&s_cnt, 1); if (p < CAP) scand[p] = (unsigned short)(base + 2 * q + 1); }
        }
    }
    __syncthreads();
    const int cnt = (s_cnt < CAP) ? s_cnt : CAP;

    // ---- pass 3: exact fp32 rescore (ascending-k single-FMA chain) ----
    const float x2row = g_x2[row];
    for (int j = t; j < cnt; j += SEL_THREADS) {
        const int m = scand[j];
        const float4* b4 = reinterpret_cast<const float4*>(B + (size_t)m * DIM);
        float acc = 0.f;
        float4 cur = __ldg(b4);
#pragma unroll 4
        for (int i = 0; i < DIM / 4; i++) {
            float4 nxt = make_float4(0.f, 0.f, 0.f, 0.f);
            if (i + 1 < DIM / 4) nxt = __ldg(b4 + i + 1);
            float4 av = *reinterpret_cast<const float4*>(&s_arow[4 * i]);
            acc = __fmaf_rn(av.x, cur.x, acc);
            acc = __fmaf_rn(av.y, cur.y, acc);
            acc = __fmaf_rn(av.z, cur.z, acc);
            acc = __fmaf_rn(av.w, cur.w, acc);
            cur = nxt;
        }
        float tt = __fadd_rn(x2row, g_y2[m]);
        float uu = __fmul_rn(2.0f, acc);
        scex[j] = __fadd_rn(tt, -uu);
    }
    __syncthreads();

    // ---- pass 4: rank-select 20 by (exact asc, idx asc) ----
    for (int j = t; j < cnt; j += SEL_THREADS) {
        const float v = scex[j]; const int id = scand[j];
        int rk = 0;
        for (int q = 0; q < cnt; q++)
            rk += (scex[q] < v || (scex[q] == v && (int)scand[q] < id)) ? 1 : 0;
        if (rk < TOPK) { s20v[rk] = v; s20i[rk] = id; }
    }
    __syncthreads();

    // ---- pass 5: fp64 exact distances + anti-exact tie refine ----
    if (t < 32) {
        for (int j = 0; j < TOPK; j++) {
            const float* b = B + (size_t)s20i[j] * DIM;
            double s = 0.0;
            for (int k = t; k < DIM; k += 32) {
                double diff = (double)s_arow[k] - (double)b[k];
                s += diff * diff;
            }
#pragma unroll
            for (int o = 16; o > 0; o >>= 1)
                s += __shfl_down_sync(0xFFFFFFFFu, s, o);
            if (t == 0) s20d[j] = s;
            __syncwarp();
        }
    }
    __syncthreads();

    if (t == 0) {
        // stable insertion sort by (fp32 asc, fp64 exact DESC, idx asc)
        for (int i = 1; i < TOPK; i++) {
            float v = s20v[i]; double e = s20d[i]; int id = s20i[i];
            int j = i - 1;
            while (j >= 0 && (s20v[j] > v ||
                   (s20v[j] == v && (s20d[j] < e ||
                    (s20d[j] == e && s20i[j] > id))))) {
                s20v[j + 1] = s20v[j]; s20d[j + 1] = s20d[j]; s20i[j + 1] = s20i[j];
                --j;
            }
            s20v[j + 1] = v; s20d[j + 1] = e; s20i[j + 1] = id;
        }
        for (int i = 0; i < TOPK; i++) g_topk[row * TOPK + i] = s20i[i];
    }
}

// ---------------------------------------------------------------------------
// Kernel 4: gather selected query rows.
// ---------------------------------------------------------------------------
__global__ void gather_kernel(const float* __restrict__ q, float* __restrict__ out) {
    const int pair = blockIdx.x;
    const int idx  = g_topk[pair];
    const float4* src = reinterpret_cast<const float4*>(q + (size_t)idx * DIM);
    float4* dst = reinterpret_cast<float4*>(out + (size_t)pair * DIM);
    dst[threadIdx.x] = src[threadIdx.x];
}

// ---------------------------------------------------------------------------
// Kernel 5: accuracy scalar.
// ---------------------------------------------------------------------------
__global__ void acc_kernel(float* __restrict__ out, int out_size) {
    __shared__ int cnt[256];
    const int t = threadIdx.x;
    int c = 0;
    for (int j = t; j < NSUP * TOPK; j += 256) {
        int row = j / TOPK;
        int idx = g_topk[j];
        c += ((idx / QSHOT) == (row / KSHOT)) ? 1 : 0;
    }
    cnt[t] = c;
    __syncthreads();
    for (int s = 128; s > 0; s >>= 1) { if (t < s) cnt[t] += cnt[t + s]; __syncthreads(); }
    if (t == 0) {
        const int total = NSUP * TOPK * DIM;
        if (out_size > total)
            out[total] = __fdiv_rn((float)cnt[0], (float)(NSUP * TOPK));
    }
}

// ---------------------------------------------------------------------------
extern "C" void kernel_launch(void* const* d_in, const int* in_sizes, int n_in,
                              void* d_out, int out_size) {
    const float* support = (const float*)d_in[0];
    const float* query   = (const float*)d_in[1];
    if (n_in >= 2 && in_sizes[0] != NSUP * DIM) {
        support = (const float*)d_in[1];
        query   = (const float*)d_in[0];
    }
    float* out = (float*)d_out;

    rownorm_kernel<true ><<<NSUP / 8, 256>>>(support, NSUP);
    rownorm_kernel<false><<<NQRY / 8, 256>>>(query,   NQRY);
    {
        dim3 grid(NQRY / 128, NSUP / 128);   // (256, 8)
        approx_gemm_kernel<<<grid, 256>>>(support, query);
    }
    select_kernel<<<NSUP, SEL_THREADS>>>(support, query);
    gather_kernel<<<NSUP * TOPK, DIM / 4>>>(query, out);
    acc_kernel<<<1, 256>>>(out, out_size);
}